// round 14
// baseline (speedup 1.0000x reference)
#include <cuda_runtime.h>

#define L_MAX   2048
#define BATCH   64
#define DDIM    256
#define CCH     512
#define NCHUNK  16
#define ROWS_PER_CHUNK (L_MAX / NCHUNK)   // 128
#define ROWS_PER_WARP  (ROWS_PER_CHUNK / 8) // 16
#define SUBTILE 8                          // rows per score/val sub-tile

#define HQ_BLOCKS 512
#define M_BLOCKS  96

#define CT_BLOCKS   BATCH
#define HARD_BLOCKS (L_MAX * BATCH / 256)   // 512

// ---- scratch (no allocations allowed) ----
__device__ float g_hq[BATCH * DDIM];
__device__ float g_M[3 * DDIM];
__device__ float g_hardU[L_MAX * BATCH];
__device__ float g_part[BATCH * NCHUNK * DDIM];
__device__ float g_denp[BATCH * NCHUNK];

__device__ __forceinline__ float ftanh(float x) {
    float e = __expf(2.0f * x);
    return 1.0f - __fdividef(2.0f, e + 1.0f);
}

// ---------------------------------------------------------------------------
// Kernel 1: prep v2 (unchanged from R13).
// ---------------------------------------------------------------------------
__global__ __launch_bounds__(256) void prep_kernel(
    const float* __restrict__ ht, const float* __restrict__ Wq,
    const float* __restrict__ Wap, const float* __restrict__ Wc,
    const float* __restrict__ bap)
{
    int warp = threadIdx.x >> 5, lane = threadIdx.x & 31;

    if (blockIdx.x < HQ_BLOCKS) {
        int gw = blockIdx.x * 8 + warp;   // [0, 4096)
        int d  = gw >> 4;
        int b0 = (gw & 15) * 4;
        const float* wqr = Wq + (size_t)d * DDIM;
        float wq[8];
#pragma unroll
        for (int i = 0; i < 8; i++) wq[i] = wqr[lane + 32 * i];

        float a0 = 0.f, a1 = 0.f, a2 = 0.f, a3 = 0.f;
#pragma unroll
        for (int i = 0; i < 8; i++) {
            int e = lane + 32 * i;
            a0 += ht[(b0 + 0) * DDIM + e] * wq[i];
            a1 += ht[(b0 + 1) * DDIM + e] * wq[i];
            a2 += ht[(b0 + 2) * DDIM + e] * wq[i];
            a3 += ht[(b0 + 3) * DDIM + e] * wq[i];
        }
#pragma unroll
        for (int off = 16; off; off >>= 1) {
            a0 += __shfl_xor_sync(0xffffffffu, a0, off);
            a1 += __shfl_xor_sync(0xffffffffu, a1, off);
            a2 += __shfl_xor_sync(0xffffffffu, a2, off);
            a3 += __shfl_xor_sync(0xffffffffu, a3, off);
        }
        if (lane < 4) {
            float a = (lane == 0) ? a0 : (lane == 1) ? a1 : (lane == 2) ? a2 : a3;
            g_hq[(b0 + lane) * DDIM + d] = a + bap[d];
        }
    } else {
        int gw = (blockIdx.x - HQ_BLOCKS) * 8 + warp;  // [0, 768)
        int dd = gw / 3;
        int k  = gw % 3;
        const float* wr = Wap + (size_t)dd * CCH;
        float m = 0.f;
#pragma unroll
        for (int i = 0; i < CCH / 32; i++) {
            int c = lane + 32 * i;
            m += wr[c] * Wc[c * 3 + k];
        }
#pragma unroll
        for (int off = 16; off; off >>= 1)
            m += __shfl_xor_sync(0xffffffffu, m, off);
        if (lane == 0) g_M[k * DDIM + dd] = m;
    }
}

// ---------------------------------------------------------------------------
// Kernel 2: main — warp-local two-phase with SUB-TILING:
//   per warp: [score 8 rows] -> [val 8 rows] -> [score 8] -> [val 8].
//   Key and val streams interleave within each warp; hreg live set halved.
//   Scoring fully unrolled so ptxas pipelines key loads across batches.
// ---------------------------------------------------------------------------
__global__ __launch_bounds__(256, 3) void main_kernel(
    const float* __restrict__ ctx_val, const float* __restrict__ ctx_key,
    const float* __restrict__ ctx_mask, const float* __restrict__ past,
    const float* __restrict__ W_attn, const float* __restrict__ b_attn)
{
    __shared__ alignas(16) float s_M[3 * DDIM];
    __shared__ alignas(16) float s_acc[8 * DDIM];
    __shared__ alignas(16) float s_past[ROWS_PER_CHUNK + 4];
    __shared__ alignas(16) float s_mask[ROWS_PER_CHUNK];
    __shared__ float s_cnt[8];

    int b = blockIdx.y, chunk = blockIdx.x;
    int w = threadIdx.x >> 5, lane = threadIdx.x & 31;
    int d0 = lane * 4;        // [0,128)
    int d1 = 128 + lane * 4;  // [128,256)

    if (threadIdx.x < 3 * DDIM / 4) {
        reinterpret_cast<float4*>(s_M)[threadIdx.x] =
            reinterpret_cast<const float4*>(g_M)[threadIdx.x];
    }
    {
        int i = threadIdx.x;
        if (i < ROWS_PER_CHUNK + 2) {
            int g = chunk * ROWS_PER_CHUNK + i - 1;
            s_past[i] = (g >= 0 && g < L_MAX) ? past[b * L_MAX + g] : 0.f;
        }
        if (i < ROWS_PER_CHUNK)
            s_mask[i] = ctx_mask[(chunk * ROWS_PER_CHUNK + i) * BATCH + b];
    }
    __syncthreads();

    float4 hq0 = *reinterpret_cast<const float4*>(&g_hq[b * DDIM + d0]);
    float4 hq1 = *reinterpret_cast<const float4*>(&g_hq[b * DDIM + d1]);
    float4 Wa0 = *reinterpret_cast<const float4*>(&W_attn[d0]);
    float4 Wa1 = *reinterpret_cast<const float4*>(&W_attn[d1]);
    float ba = b_attn[0];

    int lbase = chunk * ROWS_PER_CHUNK + w * ROWS_PER_WARP;
    size_t rowbase = ((size_t)lbase * BATCH + b) * DDIM;

    float4 acc0 = make_float4(0.f, 0.f, 0.f, 0.f);
    float4 acc1 = make_float4(0.f, 0.f, 0.f, 0.f);
    float hsum = 0.f;

    for (int st = 0; st < ROWS_PER_WARP / SUBTILE; st++) {
        int r0 = st * SUBTILE;                 // first row of sub-tile
        float hreg[SUBTILE];

        // -------- score SUBTILE rows (batch-2, fully unrolled) ----------
#pragma unroll
        for (int rb = 0; rb < SUBTILE / 2; rb++) {
            int rr = r0 + rb * 2;
            int l0 = lbase + rr;
            int lr0 = w * ROWS_PER_WARP + rr;
            size_t row0 = rowbase + (size_t)rr * (BATCH * DDIM);
            size_t row1 = row0 + (size_t)BATCH * DDIM;

            float4 ka0 = *reinterpret_cast<const float4*>(ctx_key + row0 + d0);
            float4 kb0 = *reinterpret_cast<const float4*>(ctx_key + row0 + d1);
            float4 ka1 = *reinterpret_cast<const float4*>(ctx_key + row1 + d0);
            float4 kb1 = *reinterpret_cast<const float4*>(ctx_key + row1 + d1);

            float4 m00 = *reinterpret_cast<const float4*>(&s_M[d0]);
            float4 m01 = *reinterpret_cast<const float4*>(&s_M[d1]);
            float4 m10 = *reinterpret_cast<const float4*>(&s_M[DDIM + d0]);
            float4 m11 = *reinterpret_cast<const float4*>(&s_M[DDIM + d1]);
            float4 m20 = *reinterpret_cast<const float4*>(&s_M[2 * DDIM + d0]);
            float4 m21 = *reinterpret_cast<const float4*>(&s_M[2 * DDIM + d1]);

            float pm0 = s_past[lr0],     p00 = s_past[lr0 + 1], pp0 = s_past[lr0 + 2];
            float pm1 = s_past[lr0 + 1], p01 = s_past[lr0 + 2], pp1 = s_past[lr0 + 3];

            float s0, s1;
            s0  = Wa0.x * ftanh(ka0.x + hq0.x + pm0 * m00.x + p00 * m10.x + pp0 * m20.x);
            s1  = Wa0.x * ftanh(ka1.x + hq0.x + pm1 * m00.x + p01 * m10.x + pp1 * m20.x);
            s0 += Wa0.y * ftanh(ka0.y + hq0.y + pm0 * m00.y + p00 * m10.y + pp0 * m20.y);
            s1 += Wa0.y * ftanh(ka1.y + hq0.y + pm1 * m00.y + p01 * m10.y + pp1 * m20.y);
            s0 += Wa0.z * ftanh(ka0.z + hq0.z + pm0 * m00.z + p00 * m10.z + pp0 * m20.z);
            s1 += Wa0.z * ftanh(ka1.z + hq0.z + pm1 * m00.z + p01 * m10.z + pp1 * m20.z);
            s0 += Wa0.w * ftanh(ka0.w + hq0.w + pm0 * m00.w + p00 * m10.w + pp0 * m20.w);
            s1 += Wa0.w * ftanh(ka1.w + hq0.w + pm1 * m00.w + p01 * m10.w + pp1 * m20.w);
            s0 += Wa1.x * ftanh(kb0.x + hq1.x + pm0 * m01.x + p00 * m11.x + pp0 * m21.x);
            s1 += Wa1.x * ftanh(kb1.x + hq1.x + pm1 * m01.x + p01 * m11.x + pp1 * m21.x);
            s0 += Wa1.y * ftanh(kb0.y + hq1.y + pm0 * m01.y + p00 * m11.y + pp0 * m21.y);
            s1 += Wa1.y * ftanh(kb1.y + hq1.y + pm1 * m01.y + p01 * m11.y + pp1 * m21.y);
            s0 += Wa1.z * ftanh(kb0.z + hq1.z + pm0 * m01.z + p00 * m11.z + pp0 * m21.z);
            s1 += Wa1.z * ftanh(kb1.z + hq1.z + pm1 * m01.z + p01 * m11.z + pp1 * m21.z);
            s0 += Wa1.w * ftanh(kb0.w + hq1.w + pm0 * m01.w + p00 * m11.w + pp0 * m21.w);
            s1 += Wa1.w * ftanh(kb1.w + hq1.w + pm1 * m01.w + p01 * m11.w + pp1 * m21.w);

#pragma unroll
            for (int off = 16; off; off >>= 1) {
                s0 += __shfl_xor_sync(0xffffffffu, s0, off);
                s1 += __shfl_xor_sync(0xffffffffu, s1, off);
            }

            float h0 = (s0 + ba >= 0.f) ? s_mask[lr0] : 0.f;
            float h1 = (s1 + ba >= 0.f) ? s_mask[lr0 + 1] : 0.f;
            if (lane == 0) {
                g_hardU[l0 * BATCH + b] = h0;
                g_hardU[(l0 + 1) * BATCH + b] = h1;
            }
            hreg[rb * 2]     = h0;
            hreg[rb * 2 + 1] = h1;
            hsum += h0 + h1;
        }

        // -------- val-accumulate SUBTILE rows (independent loads) -------
#pragma unroll
        for (int r = 0; r < SUBTILE; r++) {
            float h = hreg[r];
            if (h != 0.f) {   // warp-uniform; loads independent across rows
                size_t row = rowbase + (size_t)(r0 + r) * (BATCH * DDIM);
                float4 v0 = *reinterpret_cast<const float4*>(ctx_val + row + d0);
                float4 v1 = *reinterpret_cast<const float4*>(ctx_val + row + d1);
                acc0.x += h * v0.x; acc0.y += h * v0.y;
                acc0.z += h * v0.z; acc0.w += h * v0.w;
                acc1.x += h * v1.x; acc1.y += h * v1.y;
                acc1.z += h * v1.z; acc1.w += h * v1.w;
            }
        }
    }

    *reinterpret_cast<float4*>(&s_acc[w * DDIM + d0]) = acc0;
    *reinterpret_cast<float4*>(&s_acc[w * DDIM + d1]) = acc1;
    if (lane == 0) s_cnt[w] = hsum;
    __syncthreads();

    int d = threadIdx.x;
    float p = 0.f;
#pragma unroll
    for (int ww = 0; ww < 8; ww++) p += s_acc[ww * DDIM + d];
    g_part[((size_t)b * NCHUNK + chunk) * DDIM + d] = p;

    if (threadIdx.x == 0) {
        float c = 0.f;
#pragma unroll
        for (int ww = 0; ww < 8; ww++) c += s_cnt[ww];
        g_denp[b * NCHUNK + chunk] = c;
    }
}

// ---------------------------------------------------------------------------
// Kernel 3: finish v2 (unchanged).
// ---------------------------------------------------------------------------
__global__ __launch_bounds__(256) void finish_kernel(float* __restrict__ out)
{
    if (blockIdx.x < CT_BLOCKS) {
        __shared__ float s_dp[NCHUNK];
        int b = blockIdx.x, d = threadIdx.x;
        if (threadIdx.x < NCHUNK)
            s_dp[threadIdx.x] = g_denp[b * NCHUNK + threadIdx.x];
        __syncthreads();
        float den = 0.f;
#pragma unroll
        for (int c = 0; c < NCHUNK; c++) den += s_dp[c];
        float ct = 0.f;
#pragma unroll
        for (int c = 0; c < NCHUNK; c++)
            ct += g_part[((size_t)b * NCHUNK + c) * DDIM + d];
        out[b * DDIM + d] = ct / (den + 1e-10f);
    } else {
        __shared__ float s_den[BATCH];
        if (threadIdx.x < BATCH) {
            int b = threadIdx.x;
            float den = 0.f;
#pragma unroll
            for (int c = 0; c < NCHUNK; c++) den += g_denp[b * NCHUNK + c];
            s_den[b] = den + 1e-10f;
        }
        __syncthreads();
        int j = (blockIdx.x - CT_BLOCKS) * 256 + threadIdx.x;
        int b = j & (BATCH - 1);
        out[BATCH * DDIM + j] = g_hardU[j] / s_den[b];
    }
}

// ---------------------------------------------------------------------------
extern "C" void kernel_launch(void* const* d_in, const int* in_sizes, int n_in,
                              void* d_out, int out_size)
{
    (void)in_sizes; (void)n_in; (void)out_size;
    const float* ctx_val  = (const float*)d_in[0];
    const float* ctx_key  = (const float*)d_in[1];
    const float* ctx_mask = (const float*)d_in[2];
    const float* past     = (const float*)d_in[3];
    const float* ht       = (const float*)d_in[4];
    const float* Wc       = (const float*)d_in[5];
    const float* Wq       = (const float*)d_in[6];
    const float* Wap      = (const float*)d_in[7];
    const float* bap      = (const float*)d_in[8];
    const float* Wattn    = (const float*)d_in[9];
    const float* battn    = (const float*)d_in[10];
    float* out = (float*)d_out;

    prep_kernel<<<HQ_BLOCKS + M_BLOCKS, 256>>>(ht, Wq, Wap, Wc, bap);

    dim3 grid(NCHUNK, BATCH);
    main_kernel<<<grid, 256>>>(ctx_val, ctx_key, ctx_mask, past, Wattn, battn);

    finish_kernel<<<CT_BLOCKS + HARD_BLOCKS, 256>>>(out);
}

// round 15
// speedup vs baseline: 1.1471x; 1.1471x over previous
#include <cuda_runtime.h>

#define L_MAX   2048
#define BATCH   64
#define DDIM    256
#define CCH     512
#define NCHUNK  16
#define ROWS_PER_CHUNK (L_MAX / NCHUNK)   // 128
#define ROWS_PER_WARP  (ROWS_PER_CHUNK / 8) // 16

#define HQ_BLOCKS 512
#define M_BLOCKS  96

#define CT_BLOCKS   BATCH
#define HARD_BLOCKS (L_MAX * BATCH / 256)   // 512

// ---- scratch (no allocations allowed) ----
__device__ float g_hq[BATCH * DDIM];
__device__ float g_M[3 * DDIM];
__device__ float g_hardU[L_MAX * BATCH];
__device__ float g_part[BATCH * NCHUNK * DDIM];
__device__ float g_denp[BATCH * NCHUNK];

__device__ __forceinline__ float ftanh(float x) {
    float e = __expf(2.0f * x);
    return 1.0f - __fdividef(2.0f, e + 1.0f);
}

// ---------------------------------------------------------------------------
// Kernel 1: prep v2 (unchanged from R13).
// ---------------------------------------------------------------------------
__global__ __launch_bounds__(256) void prep_kernel(
    const float* __restrict__ ht, const float* __restrict__ Wq,
    const float* __restrict__ Wap, const float* __restrict__ Wc,
    const float* __restrict__ bap)
{
    int warp = threadIdx.x >> 5, lane = threadIdx.x & 31;

    if (blockIdx.x < HQ_BLOCKS) {
        int gw = blockIdx.x * 8 + warp;   // [0, 4096)
        int d  = gw >> 4;
        int b0 = (gw & 15) * 4;
        const float* wqr = Wq + (size_t)d * DDIM;
        float wq[8];
#pragma unroll
        for (int i = 0; i < 8; i++) wq[i] = wqr[lane + 32 * i];

        float a0 = 0.f, a1 = 0.f, a2 = 0.f, a3 = 0.f;
#pragma unroll
        for (int i = 0; i < 8; i++) {
            int e = lane + 32 * i;
            a0 += ht[(b0 + 0) * DDIM + e] * wq[i];
            a1 += ht[(b0 + 1) * DDIM + e] * wq[i];
            a2 += ht[(b0 + 2) * DDIM + e] * wq[i];
            a3 += ht[(b0 + 3) * DDIM + e] * wq[i];
        }
#pragma unroll
        for (int off = 16; off; off >>= 1) {
            a0 += __shfl_xor_sync(0xffffffffu, a0, off);
            a1 += __shfl_xor_sync(0xffffffffu, a1, off);
            a2 += __shfl_xor_sync(0xffffffffu, a2, off);
            a3 += __shfl_xor_sync(0xffffffffu, a3, off);
        }
        if (lane < 4) {
            float a = (lane == 0) ? a0 : (lane == 1) ? a1 : (lane == 2) ? a2 : a3;
            g_hq[(b0 + lane) * DDIM + d] = a + bap[d];
        }
    } else {
        int gw = (blockIdx.x - HQ_BLOCKS) * 8 + warp;  // [0, 768)
        int dd = gw / 3;
        int k  = gw % 3;
        const float* wr = Wap + (size_t)dd * CCH;
        float m = 0.f;
#pragma unroll
        for (int i = 0; i < CCH / 32; i++) {
            int c = lane + 32 * i;
            m += wr[c] * Wc[c * 3 + k];
        }
#pragma unroll
        for (int off = 16; off; off >>= 1)
            m += __shfl_xor_sync(0xffffffffu, m, off);
        if (lane == 0) g_M[k * DDIM + dd] = m;
    }
}

// ---------------------------------------------------------------------------
// Kernel 2: main — R13 warp-local two-phase (full 16-row decoupling), but
// Phase A stores only a 16-bit predicate mask (1 reg instead of hreg[16]);
// Phase B rebuilds h from s_mask. Freed regs buy 4 blocks/SM occupancy.
// ---------------------------------------------------------------------------
__global__ __launch_bounds__(256, 4) void main_kernel(
    const float* __restrict__ ctx_val, const float* __restrict__ ctx_key,
    const float* __restrict__ ctx_mask, const float* __restrict__ past,
    const float* __restrict__ W_attn, const float* __restrict__ b_attn)
{
    __shared__ alignas(16) float s_M[3 * DDIM];
    __shared__ alignas(16) float s_acc[8 * DDIM];
    __shared__ alignas(16) float s_past[ROWS_PER_CHUNK + 4];
    __shared__ alignas(16) float s_mask[ROWS_PER_CHUNK];
    __shared__ float s_cnt[8];

    int b = blockIdx.y, chunk = blockIdx.x;
    int w = threadIdx.x >> 5, lane = threadIdx.x & 31;
    int d0 = lane * 4;        // [0,128)
    int d1 = 128 + lane * 4;  // [128,256)

    if (threadIdx.x < 3 * DDIM / 4) {
        reinterpret_cast<float4*>(s_M)[threadIdx.x] =
            reinterpret_cast<const float4*>(g_M)[threadIdx.x];
    }
    {
        int i = threadIdx.x;
        if (i < ROWS_PER_CHUNK + 2) {
            int g = chunk * ROWS_PER_CHUNK + i - 1;
            s_past[i] = (g >= 0 && g < L_MAX) ? past[b * L_MAX + g] : 0.f;
        }
        if (i < ROWS_PER_CHUNK)
            s_mask[i] = ctx_mask[(chunk * ROWS_PER_CHUNK + i) * BATCH + b];
    }
    __syncthreads();

    float4 hq0 = *reinterpret_cast<const float4*>(&g_hq[b * DDIM + d0]);
    float4 hq1 = *reinterpret_cast<const float4*>(&g_hq[b * DDIM + d1]);
    float4 Wa0 = *reinterpret_cast<const float4*>(&W_attn[d0]);
    float4 Wa1 = *reinterpret_cast<const float4*>(&W_attn[d1]);
    float ba = b_attn[0];

    int lbase = chunk * ROWS_PER_CHUNK + w * ROWS_PER_WARP;
    int wbase = w * ROWS_PER_WARP;
    size_t rowbase = ((size_t)lbase * BATCH + b) * DDIM;

    // ---------------- Phase A: score 16 rows -> predicate bits -----------
    unsigned pbits = 0;

#pragma unroll 2
    for (int rb = 0; rb < ROWS_PER_WARP / 2; rb++) {
        int l0 = lbase + rb * 2;
        int lr0 = wbase + rb * 2;
        size_t row0 = rowbase + (size_t)(rb * 2) * (BATCH * DDIM);
        size_t row1 = row0 + (size_t)BATCH * DDIM;

        float4 ka0 = *reinterpret_cast<const float4*>(ctx_key + row0 + d0);
        float4 kb0 = *reinterpret_cast<const float4*>(ctx_key + row0 + d1);
        float4 ka1 = *reinterpret_cast<const float4*>(ctx_key + row1 + d0);
        float4 kb1 = *reinterpret_cast<const float4*>(ctx_key + row1 + d1);

        float4 m00 = *reinterpret_cast<const float4*>(&s_M[d0]);
        float4 m01 = *reinterpret_cast<const float4*>(&s_M[d1]);
        float4 m10 = *reinterpret_cast<const float4*>(&s_M[DDIM + d0]);
        float4 m11 = *reinterpret_cast<const float4*>(&s_M[DDIM + d1]);
        float4 m20 = *reinterpret_cast<const float4*>(&s_M[2 * DDIM + d0]);
        float4 m21 = *reinterpret_cast<const float4*>(&s_M[2 * DDIM + d1]);

        float pm0 = s_past[lr0],     p00 = s_past[lr0 + 1], pp0 = s_past[lr0 + 2];
        float pm1 = s_past[lr0 + 1], p01 = s_past[lr0 + 2], pp1 = s_past[lr0 + 3];

        float s0, s1;
        s0  = Wa0.x * ftanh(ka0.x + hq0.x + pm0 * m00.x + p00 * m10.x + pp0 * m20.x);
        s1  = Wa0.x * ftanh(ka1.x + hq0.x + pm1 * m00.x + p01 * m10.x + pp1 * m20.x);
        s0 += Wa0.y * ftanh(ka0.y + hq0.y + pm0 * m00.y + p00 * m10.y + pp0 * m20.y);
        s1 += Wa0.y * ftanh(ka1.y + hq0.y + pm1 * m00.y + p01 * m10.y + pp1 * m20.y);
        s0 += Wa0.z * ftanh(ka0.z + hq0.z + pm0 * m00.z + p00 * m10.z + pp0 * m20.z);
        s1 += Wa0.z * ftanh(ka1.z + hq0.z + pm1 * m00.z + p01 * m10.z + pp1 * m20.z);
        s0 += Wa0.w * ftanh(ka0.w + hq0.w + pm0 * m00.w + p00 * m10.w + pp0 * m20.w);
        s1 += Wa0.w * ftanh(ka1.w + hq0.w + pm1 * m00.w + p01 * m10.w + pp1 * m20.w);
        s0 += Wa1.x * ftanh(kb0.x + hq1.x + pm0 * m01.x + p00 * m11.x + pp0 * m21.x);
        s1 += Wa1.x * ftanh(kb1.x + hq1.x + pm1 * m01.x + p01 * m11.x + pp1 * m21.x);
        s0 += Wa1.y * ftanh(kb0.y + hq1.y + pm0 * m01.y + p00 * m11.y + pp0 * m21.y);
        s1 += Wa1.y * ftanh(kb1.y + hq1.y + pm1 * m01.y + p01 * m11.y + pp1 * m21.y);
        s0 += Wa1.z * ftanh(kb0.z + hq1.z + pm0 * m01.z + p00 * m11.z + pp0 * m21.z);
        s1 += Wa1.z * ftanh(kb1.z + hq1.z + pm1 * m01.z + p01 * m11.z + pp1 * m21.z);
        s0 += Wa1.w * ftanh(kb0.w + hq1.w + pm0 * m01.w + p00 * m11.w + pp0 * m21.w);
        s1 += Wa1.w * ftanh(kb1.w + hq1.w + pm1 * m01.w + p01 * m11.w + pp1 * m21.w);

#pragma unroll
        for (int off = 16; off; off >>= 1) {
            s0 += __shfl_xor_sync(0xffffffffu, s0, off);
            s1 += __shfl_xor_sync(0xffffffffu, s1, off);
        }

        float h0 = (s0 + ba >= 0.f) ? s_mask[lr0] : 0.f;
        float h1 = (s1 + ba >= 0.f) ? s_mask[lr0 + 1] : 0.f;
        if (lane == 0) {
            g_hardU[l0 * BATCH + b] = h0;
            g_hardU[(l0 + 1) * BATCH + b] = h1;
        }
        if (h0 != 0.f) pbits |= 1u << (rb * 2);
        if (h1 != 0.f) pbits |= 1u << (rb * 2 + 1);
    }

    // ---------------- Phase B: independent conditional val loads ---------
    float4 acc0 = make_float4(0.f, 0.f, 0.f, 0.f);
    float4 acc1 = make_float4(0.f, 0.f, 0.f, 0.f);
    float hsum = 0.f;
#pragma unroll
    for (int r = 0; r < ROWS_PER_WARP; r++) {
        if (pbits & (1u << r)) {   // warp-uniform
            float h = s_mask[wbase + r];
            hsum += h;
            size_t row = rowbase + (size_t)r * (BATCH * DDIM);
            float4 v0 = *reinterpret_cast<const float4*>(ctx_val + row + d0);
            float4 v1 = *reinterpret_cast<const float4*>(ctx_val + row + d1);
            acc0.x += h * v0.x; acc0.y += h * v0.y;
            acc0.z += h * v0.z; acc0.w += h * v0.w;
            acc1.x += h * v1.x; acc1.y += h * v1.y;
            acc1.z += h * v1.z; acc1.w += h * v1.w;
        }
    }

    *reinterpret_cast<float4*>(&s_acc[w * DDIM + d0]) = acc0;
    *reinterpret_cast<float4*>(&s_acc[w * DDIM + d1]) = acc1;
    if (lane == 0) s_cnt[w] = hsum;
    __syncthreads();

    int d = threadIdx.x;
    float p = 0.f;
#pragma unroll
    for (int ww = 0; ww < 8; ww++) p += s_acc[ww * DDIM + d];
    g_part[((size_t)b * NCHUNK + chunk) * DDIM + d] = p;

    if (threadIdx.x == 0) {
        float c = 0.f;
#pragma unroll
        for (int ww = 0; ww < 8; ww++) c += s_cnt[ww];
        g_denp[b * NCHUNK + chunk] = c;
    }
}

// ---------------------------------------------------------------------------
// Kernel 3: finish v2 (unchanged).
// ---------------------------------------------------------------------------
__global__ __launch_bounds__(256) void finish_kernel(float* __restrict__ out)
{
    if (blockIdx.x < CT_BLOCKS) {
        __shared__ float s_dp[NCHUNK];
        int b = blockIdx.x, d = threadIdx.x;
        if (threadIdx.x < NCHUNK)
            s_dp[threadIdx.x] = g_denp[b * NCHUNK + threadIdx.x];
        __syncthreads();
        float den = 0.f;
#pragma unroll
        for (int c = 0; c < NCHUNK; c++) den += s_dp[c];
        float ct = 0.f;
#pragma unroll
        for (int c = 0; c < NCHUNK; c++)
            ct += g_part[((size_t)b * NCHUNK + c) * DDIM + d];
        out[b * DDIM + d] = ct / (den + 1e-10f);
    } else {
        __shared__ float s_den[BATCH];
        if (threadIdx.x < BATCH) {
            int b = threadIdx.x;
            float den = 0.f;
#pragma unroll
            for (int c = 0; c < NCHUNK; c++) den += g_denp[b * NCHUNK + c];
            s_den[b] = den + 1e-10f;
        }
        __syncthreads();
        int j = (blockIdx.x - CT_BLOCKS) * 256 + threadIdx.x;
        int b = j & (BATCH - 1);
        out[BATCH * DDIM + j] = g_hardU[j] / s_den[b];
    }
}

// ---------------------------------------------------------------------------
extern "C" void kernel_launch(void* const* d_in, const int* in_sizes, int n_in,
                              void* d_out, int out_size)
{
    (void)in_sizes; (void)n_in; (void)out_size;
    const float* ctx_val  = (const float*)d_in[0];
    const float* ctx_key  = (const float*)d_in[1];
    const float* ctx_mask = (const float*)d_in[2];
    const float* past     = (const float*)d_in[3];
    const float* ht       = (const float*)d_in[4];
    const float* Wc       = (const float*)d_in[5];
    const float* Wq       = (const float*)d_in[6];
    const float* Wap      = (const float*)d_in[7];
    const float* bap      = (const float*)d_in[8];
    const float* Wattn    = (const float*)d_in[9];
    const float* battn    = (const float*)d_in[10];
    float* out = (float*)d_out;

    prep_kernel<<<HQ_BLOCKS + M_BLOCKS, 256>>>(ht, Wq, Wap, Wc, bap);

    dim3 grid(NCHUNK, BATCH);
    main_kernel<<<grid, 256>>>(ctx_val, ctx_key, ctx_mask, past, Wattn, battn);

    finish_kernel<<<CT_BLOCKS + HARD_BLOCKS, 256>>>(out);
}

// round 16
// speedup vs baseline: 1.1892x; 1.0367x over previous
#include <cuda_runtime.h>

#define L_MAX   2048
#define BATCH   64
#define DDIM    256
#define CCH     512
#define NCHUNK  16
#define ROWS_PER_CHUNK (L_MAX / NCHUNK)   // 128
#define ROWS_PER_WARP  (ROWS_PER_CHUNK / 8) // 16

#define HQ_BLOCKS 512
#define M_BLOCKS  96

#define CT_BLOCKS   BATCH
#define HARD_BLOCKS (L_MAX * BATCH / 256)   // 512

// ---- scratch (no allocations allowed) ----
__device__ float g_hq[BATCH * DDIM];
__device__ float g_M[3 * DDIM];
__device__ float g_hardU[L_MAX * BATCH];
__device__ float g_part[BATCH * NCHUNK * DDIM];
__device__ float g_denp[BATCH * NCHUNK];

// Wu*tanh(xu) + Wv*tanh(xv) with ONE shared rcp:
//   = (Wu+Wv) - 2*(Wu*dv + Wv*du)/(du*dv),  du=e^{2xu}+1, dv=e^{2xv}+1
// 3 MUFU (2 EX2 + 1 RCP) instead of 4.
__device__ __forceinline__ float wtanh2(float Wu, float xu, float Wv, float xv,
                                        float Wsum) {
    float du = __expf(2.0f * xu) + 1.0f;
    float dv = __expf(2.0f * xv) + 1.0f;
    return Wsum - 2.0f * __fdividef(fmaf(Wu, dv, Wv * du), du * dv);
}

// ---------------------------------------------------------------------------
// Kernel 1: prep v2 (unchanged from R13).
// ---------------------------------------------------------------------------
__global__ __launch_bounds__(256) void prep_kernel(
    const float* __restrict__ ht, const float* __restrict__ Wq,
    const float* __restrict__ Wap, const float* __restrict__ Wc,
    const float* __restrict__ bap)
{
    int warp = threadIdx.x >> 5, lane = threadIdx.x & 31;

    if (blockIdx.x < HQ_BLOCKS) {
        int gw = blockIdx.x * 8 + warp;   // [0, 4096)
        int d  = gw >> 4;
        int b0 = (gw & 15) * 4;
        const float* wqr = Wq + (size_t)d * DDIM;
        float wq[8];
#pragma unroll
        for (int i = 0; i < 8; i++) wq[i] = wqr[lane + 32 * i];

        float a0 = 0.f, a1 = 0.f, a2 = 0.f, a3 = 0.f;
#pragma unroll
        for (int i = 0; i < 8; i++) {
            int e = lane + 32 * i;
            a0 += ht[(b0 + 0) * DDIM + e] * wq[i];
            a1 += ht[(b0 + 1) * DDIM + e] * wq[i];
            a2 += ht[(b0 + 2) * DDIM + e] * wq[i];
            a3 += ht[(b0 + 3) * DDIM + e] * wq[i];
        }
#pragma unroll
        for (int off = 16; off; off >>= 1) {
            a0 += __shfl_xor_sync(0xffffffffu, a0, off);
            a1 += __shfl_xor_sync(0xffffffffu, a1, off);
            a2 += __shfl_xor_sync(0xffffffffu, a2, off);
            a3 += __shfl_xor_sync(0xffffffffu, a3, off);
        }
        if (lane < 4) {
            float a = (lane == 0) ? a0 : (lane == 1) ? a1 : (lane == 2) ? a2 : a3;
            g_hq[(b0 + lane) * DDIM + d] = a + bap[d];
        }
    } else {
        int gw = (blockIdx.x - HQ_BLOCKS) * 8 + warp;  // [0, 768)
        int dd = gw / 3;
        int k  = gw % 3;
        const float* wr = Wap + (size_t)dd * CCH;
        float m = 0.f;
#pragma unroll
        for (int i = 0; i < CCH / 32; i++) {
            int c = lane + 32 * i;
            m += wr[c] * Wc[c * 3 + k];
        }
#pragma unroll
        for (int off = 16; off; off >>= 1)
            m += __shfl_xor_sync(0xffffffffu, m, off);
        if (lane == 0) g_M[k * DDIM + dd] = m;
    }
}

// per-element score argument
#define ARG(K, HQ, M0v, M1v, M2v, PM, P0, PP) \
    ((K) + (HQ) + (PM) * (M0v) + (P0) * (M1v) + (PP) * (M2v))

// ---------------------------------------------------------------------------
// Kernel 2: main — R15 structure (16-row two-phase, pbits, occ 4), with
// paired-rcp tanh: 12 MUFU per thread-row instead of 16.
// ---------------------------------------------------------------------------
__global__ __launch_bounds__(256, 4) void main_kernel(
    const float* __restrict__ ctx_val, const float* __restrict__ ctx_key,
    const float* __restrict__ ctx_mask, const float* __restrict__ past,
    const float* __restrict__ W_attn, const float* __restrict__ b_attn)
{
    __shared__ alignas(16) float s_M[3 * DDIM];
    __shared__ alignas(16) float s_acc[8 * DDIM];
    __shared__ alignas(16) float s_past[ROWS_PER_CHUNK + 4];
    __shared__ alignas(16) float s_mask[ROWS_PER_CHUNK];
    __shared__ float s_cnt[8];

    int b = blockIdx.y, chunk = blockIdx.x;
    int w = threadIdx.x >> 5, lane = threadIdx.x & 31;
    int d0 = lane * 4;        // [0,128)
    int d1 = 128 + lane * 4;  // [128,256)

    if (threadIdx.x < 3 * DDIM / 4) {
        reinterpret_cast<float4*>(s_M)[threadIdx.x] =
            reinterpret_cast<const float4*>(g_M)[threadIdx.x];
    }
    {
        int i = threadIdx.x;
        if (i < ROWS_PER_CHUNK + 2) {
            int g = chunk * ROWS_PER_CHUNK + i - 1;
            s_past[i] = (g >= 0 && g < L_MAX) ? past[b * L_MAX + g] : 0.f;
        }
        if (i < ROWS_PER_CHUNK)
            s_mask[i] = ctx_mask[(chunk * ROWS_PER_CHUNK + i) * BATCH + b];
    }
    __syncthreads();

    float4 hq0 = *reinterpret_cast<const float4*>(&g_hq[b * DDIM + d0]);
    float4 hq1 = *reinterpret_cast<const float4*>(&g_hq[b * DDIM + d1]);
    float4 Wa0 = *reinterpret_cast<const float4*>(&W_attn[d0]);
    float4 Wa1 = *reinterpret_cast<const float4*>(&W_attn[d1]);
    float ba = b_attn[0];

    // loop-invariant pair sums
    float wsA = Wa0.x + Wa0.y;
    float wsB = Wa0.z + Wa0.w;
    float wsC = Wa1.x + Wa1.y;
    float wsD = Wa1.z + Wa1.w;

    int lbase = chunk * ROWS_PER_CHUNK + w * ROWS_PER_WARP;
    int wbase = w * ROWS_PER_WARP;
    size_t rowbase = ((size_t)lbase * BATCH + b) * DDIM;

    // ---------------- Phase A: score 16 rows -> predicate bits -----------
    unsigned pbits = 0;

#pragma unroll 2
    for (int rb = 0; rb < ROWS_PER_WARP / 2; rb++) {
        int l0 = lbase + rb * 2;
        int lr0 = wbase + rb * 2;
        size_t row0 = rowbase + (size_t)(rb * 2) * (BATCH * DDIM);
        size_t row1 = row0 + (size_t)BATCH * DDIM;

        float4 ka0 = *reinterpret_cast<const float4*>(ctx_key + row0 + d0);
        float4 kb0 = *reinterpret_cast<const float4*>(ctx_key + row0 + d1);
        float4 ka1 = *reinterpret_cast<const float4*>(ctx_key + row1 + d0);
        float4 kb1 = *reinterpret_cast<const float4*>(ctx_key + row1 + d1);

        float4 m00 = *reinterpret_cast<const float4*>(&s_M[d0]);
        float4 m01 = *reinterpret_cast<const float4*>(&s_M[d1]);
        float4 m10 = *reinterpret_cast<const float4*>(&s_M[DDIM + d0]);
        float4 m11 = *reinterpret_cast<const float4*>(&s_M[DDIM + d1]);
        float4 m20 = *reinterpret_cast<const float4*>(&s_M[2 * DDIM + d0]);
        float4 m21 = *reinterpret_cast<const float4*>(&s_M[2 * DDIM + d1]);

        float pm0 = s_past[lr0],     p00 = s_past[lr0 + 1], pp0 = s_past[lr0 + 2];
        float pm1 = s_past[lr0 + 1], p01 = s_past[lr0 + 2], pp1 = s_past[lr0 + 3];

        float s0, s1;
        s0  = wtanh2(Wa0.x, ARG(ka0.x, hq0.x, m00.x, m10.x, m20.x, pm0, p00, pp0),
                     Wa0.y, ARG(ka0.y, hq0.y, m00.y, m10.y, m20.y, pm0, p00, pp0), wsA);
        s1  = wtanh2(Wa0.x, ARG(ka1.x, hq0.x, m00.x, m10.x, m20.x, pm1, p01, pp1),
                     Wa0.y, ARG(ka1.y, hq0.y, m00.y, m10.y, m20.y, pm1, p01, pp1), wsA);
        s0 += wtanh2(Wa0.z, ARG(ka0.z, hq0.z, m00.z, m10.z, m20.z, pm0, p00, pp0),
                     Wa0.w, ARG(ka0.w, hq0.w, m00.w, m10.w, m20.w, pm0, p00, pp0), wsB);
        s1 += wtanh2(Wa0.z, ARG(ka1.z, hq0.z, m00.z, m10.z, m20.z, pm1, p01, pp1),
                     Wa0.w, ARG(ka1.w, hq0.w, m00.w, m10.w, m20.w, pm1, p01, pp1), wsB);
        s0 += wtanh2(Wa1.x, ARG(kb0.x, hq1.x, m01.x, m11.x, m21.x, pm0, p00, pp0),
                     Wa1.y, ARG(kb0.y, hq1.y, m01.y, m11.y, m21.y, pm0, p00, pp0), wsC);
        s1 += wtanh2(Wa1.x, ARG(kb1.x, hq1.x, m01.x, m11.x, m21.x, pm1, p01, pp1),
                     Wa1.y, ARG(kb1.y, hq1.y, m01.y, m11.y, m21.y, pm1, p01, pp1), wsC);
        s0 += wtanh2(Wa1.z, ARG(kb0.z, hq1.z, m01.z, m11.z, m21.z, pm0, p00, pp0),
                     Wa1.w, ARG(kb0.w, hq1.w, m01.w, m11.w, m21.w, pm0, p00, pp0), wsD);
        s1 += wtanh2(Wa1.z, ARG(kb1.z, hq1.z, m01.z, m11.z, m21.z, pm1, p01, pp1),
                     Wa1.w, ARG(kb1.w, hq1.w, m01.w, m11.w, m21.w, pm1, p01, pp1), wsD);

#pragma unroll
        for (int off = 16; off; off >>= 1) {
            s0 += __shfl_xor_sync(0xffffffffu, s0, off);
            s1 += __shfl_xor_sync(0xffffffffu, s1, off);
        }

        float h0 = (s0 + ba >= 0.f) ? s_mask[lr0] : 0.f;
        float h1 = (s1 + ba >= 0.f) ? s_mask[lr0 + 1] : 0.f;
        if (lane == 0) {
            g_hardU[l0 * BATCH + b] = h0;
            g_hardU[(l0 + 1) * BATCH + b] = h1;
        }
        if (h0 != 0.f) pbits |= 1u << (rb * 2);
        if (h1 != 0.f) pbits |= 1u << (rb * 2 + 1);
    }

    // ---------------- Phase B: independent conditional val loads ---------
    float4 acc0 = make_float4(0.f, 0.f, 0.f, 0.f);
    float4 acc1 = make_float4(0.f, 0.f, 0.f, 0.f);
    float hsum = 0.f;
#pragma unroll
    for (int r = 0; r < ROWS_PER_WARP; r++) {
        if (pbits & (1u << r)) {   // warp-uniform
            float h = s_mask[wbase + r];
            hsum += h;
            size_t row = rowbase + (size_t)r * (BATCH * DDIM);
            float4 v0 = *reinterpret_cast<const float4*>(ctx_val + row + d0);
            float4 v1 = *reinterpret_cast<const float4*>(ctx_val + row + d1);
            acc0.x += h * v0.x; acc0.y += h * v0.y;
            acc0.z += h * v0.z; acc0.w += h * v0.w;
            acc1.x += h * v1.x; acc1.y += h * v1.y;
            acc1.z += h * v1.z; acc1.w += h * v1.w;
        }
    }

    *reinterpret_cast<float4*>(&s_acc[w * DDIM + d0]) = acc0;
    *reinterpret_cast<float4*>(&s_acc[w * DDIM + d1]) = acc1;
    if (lane == 0) s_cnt[w] = hsum;
    __syncthreads();

    int d = threadIdx.x;
    float p = 0.f;
#pragma unroll
    for (int ww = 0; ww < 8; ww++) p += s_acc[ww * DDIM + d];
    g_part[((size_t)b * NCHUNK + chunk) * DDIM + d] = p;

    if (threadIdx.x == 0) {
        float c = 0.f;
#pragma unroll
        for (int ww = 0; ww < 8; ww++) c += s_cnt[ww];
        g_denp[b * NCHUNK + chunk] = c;
    }
}

// ---------------------------------------------------------------------------
// Kernel 3: finish v2 (unchanged).
// ---------------------------------------------------------------------------
__global__ __launch_bounds__(256) void finish_kernel(float* __restrict__ out)
{
    if (blockIdx.x < CT_BLOCKS) {
        __shared__ float s_dp[NCHUNK];
        int b = blockIdx.x, d = threadIdx.x;
        if (threadIdx.x < NCHUNK)
            s_dp[threadIdx.x] = g_denp[b * NCHUNK + threadIdx.x];
        __syncthreads();
        float den = 0.f;
#pragma unroll
        for (int c = 0; c < NCHUNK; c++) den += s_dp[c];
        float ct = 0.f;
#pragma unroll
        for (int c = 0; c < NCHUNK; c++)
            ct += g_part[((size_t)b * NCHUNK + c) * DDIM + d];
        out[b * DDIM + d] = ct / (den + 1e-10f);
    } else {
        __shared__ float s_den[BATCH];
        if (threadIdx.x < BATCH) {
            int b = threadIdx.x;
            float den = 0.f;
#pragma unroll
            for (int c = 0; c < NCHUNK; c++) den += g_denp[b * NCHUNK + c];
            s_den[b] = den + 1e-10f;
        }
        __syncthreads();
        int j = (blockIdx.x - CT_BLOCKS) * 256 + threadIdx.x;
        int b = j & (BATCH - 1);
        out[BATCH * DDIM + j] = g_hardU[j] / s_den[b];
    }
}

// ---------------------------------------------------------------------------
extern "C" void kernel_launch(void* const* d_in, const int* in_sizes, int n_in,
                              void* d_out, int out_size)
{
    (void)in_sizes; (void)n_in; (void)out_size;
    const float* ctx_val  = (const float*)d_in[0];
    const float* ctx_key  = (const float*)d_in[1];
    const float* ctx_mask = (const float*)d_in[2];
    const float* past     = (const float*)d_in[3];
    const float* ht       = (const float*)d_in[4];
    const float* Wc       = (const float*)d_in[5];
    const float* Wq       = (const float*)d_in[6];
    const float* Wap      = (const float*)d_in[7];
    const float* bap      = (const float*)d_in[8];
    const float* Wattn    = (const float*)d_in[9];
    const float* battn    = (const float*)d_in[10];
    float* out = (float*)d_out;

    prep_kernel<<<HQ_BLOCKS + M_BLOCKS, 256>>>(ht, Wq, Wap, Wc, bap);

    dim3 grid(NCHUNK, BATCH);
    main_kernel<<<grid, 256>>>(ctx_val, ctx_key, ctx_mask, past, Wattn, battn);

    finish_kernel<<<CT_BLOCKS + HARD_BLOCKS, 256>>>(out);
}